// round 2
// baseline (speedup 1.0000x reference)
#include <cuda_runtime.h>
#include <math.h>

// Problem constants
#define N_NODES 102400
#define N_EDGES 819200
#define N_GRAPH 512
#define NPG     200
#define BB      8
#define TT      64
#define DD      128
#define NH      4
#define DH      32
#define NL      4
#define HID     64

// ---------------- scratch (device globals; no allocation) ----------------
__device__ __align__(256) int   g_indeg [N_NODES];
__device__ __align__(256) int   g_cursor[N_NODES];
__device__ __align__(256) int   g_rowp  [N_NODES + 1];
__device__ __align__(256) int   g_gtot  [N_GRAPH];
__device__ __align__(256) int   g_gbase [N_GRAPH];
__device__ __align__(256) int   g_ecol  [N_EDGES];
__device__ __align__(256) float g_enorm [N_EDGES];
__device__ __align__(256) float g_dinv  [N_NODES];
__device__ __align__(256) float g_seq [BB * TT * DD];
__device__ __align__(256) float g_qkv [BB * TT * 3 * DD];
__device__ __align__(256) float g_att [BB * TT * DD];
__device__ __align__(256) float g_ffn [BB * TT * 4 * DD];

// =============== CSR prep ===============
__global__ void k_prep_zero() {
    int i = blockIdx.x * blockDim.x + threadIdx.x;
    if (i < N_NODES) { g_indeg[i] = 0; g_cursor[i] = 0; }
}
__global__ void k_count(const int* __restrict__ dst) {
    int e = blockIdx.x * blockDim.x + threadIdx.x;
    if (e < N_EDGES) atomicAdd(&g_indeg[dst[e]], 1);
}
__global__ void k_dinv() {
    int i = blockIdx.x * blockDim.x + threadIdx.x;
    if (i < N_NODES) g_dinv[i] = rsqrtf((float)(g_indeg[i] + 1));
}
// per-graph exclusive scan of 200 in-degrees -> local offsets, + graph totals
__global__ void k_scan1() {
    __shared__ int buf0[256], buf1[256];
    int g = blockIdx.x, tid = threadIdx.x;
    int v = (tid < NPG) ? g_indeg[g * NPG + tid] : 0;
    int* a = buf0; int* b = buf1;
    a[tid] = v; __syncthreads();
    #pragma unroll
    for (int o = 1; o < 256; o <<= 1) {
        int xv = a[tid];
        if (tid >= o) xv += a[tid - o];
        b[tid] = xv; __syncthreads();
        int* t = a; a = b; b = t;
    }
    if (tid < NPG) g_rowp[g * NPG + tid] = a[tid] - v;   // exclusive, graph-local
    if (tid == NPG - 1) g_gtot[g] = a[tid];
}
// exclusive scan over 512 graph totals
__global__ void k_scan2() {
    __shared__ int buf0[512], buf1[512];
    int tid = threadIdx.x;
    int v = g_gtot[tid];
    int* a = buf0; int* b = buf1;
    a[tid] = v; __syncthreads();
    #pragma unroll
    for (int o = 1; o < 512; o <<= 1) {
        int xv = a[tid];
        if (tid >= o) xv += a[tid - o];
        b[tid] = xv; __syncthreads();
        int* t = a; a = b; b = t;
    }
    g_gbase[tid] = a[tid] - v;
}
__global__ void k_scan3() {
    int i = blockIdx.x * blockDim.x + threadIdx.x;
    if (i < N_NODES) g_rowp[i] += g_gbase[i / NPG];
    if (i == 0) g_rowp[N_NODES] = N_EDGES;
}
__global__ void k_scatter(const int* __restrict__ src, const int* __restrict__ dst) {
    int e = blockIdx.x * blockDim.x + threadIdx.x;
    if (e < N_EDGES) {
        int s = src[e], d = dst[e];
        int pos = g_rowp[d] + atomicAdd(&g_cursor[d], 1);
        g_ecol[pos]  = s - (d / NPG) * NPG;       // graph-local src
        g_enorm[pos] = g_dinv[s] * g_dinv[d];
    }
}

// =============== GNN mega-kernel: one block per graph ===============
#define SM_TOTAL (4096 + 12800 + 12800 + 128 + 64*6 + 200 + 200 + 400 + 400 + 256)

__global__ void __launch_bounds__(256, 1) k_mega(
    const float* __restrict__ x,
    const float* __restrict__ W1, const float* __restrict__ b1,
    const float* __restrict__ g1, const float* __restrict__ be1,
    const float* __restrict__ W2, const float* __restrict__ b2,
    const float* __restrict__ g2, const float* __restrict__ be2,
    const float* __restrict__ W3, const float* __restrict__ b3)
{
    extern __shared__ float sm[];
    float* sW2  = sm;
    float* sh   = sW2 + 4096;
    float* sag  = sh + 12800;
    float* sW1  = sag + 12800;
    float* sb1  = sW1 + 128;
    float* sg1  = sb1 + 64;
    float* sbe1 = sg1 + 64;
    float* sb2  = sbe1 + 64;
    float* sg2  = sb2 + 64;
    float* sbe2 = sg2 + 64;
    float* sdv  = sbe2 + 64;
    float* swt  = sdv + 200;
    float* sx   = swt + 200;
    float* sa1  = sx + 400;
    float* smean= sa1 + 400;

    int g = blockIdx.x, tid = threadIdx.x;
    int nb = g * NPG;
    int wid = tid >> 5, lane = tid & 31;

    for (int i = tid; i < 4096; i += 256) sW2[i] = W2[i];
    if (tid < 128) sW1[tid] = W1[tid];
    if (tid < 64) {
        sb1[tid] = b1[tid]; sg1[tid] = g1[tid]; sbe1[tid] = be1[tid];
        sb2[tid] = b2[tid]; sg2[tid] = g2[tid]; sbe2[tid] = be2[tid];
    }
    for (int i = tid; i < NPG; i += 256) {
        sdv[i] = g_dinv[nb + i];
        sx[2 * i]     = x[(nb + i) * 2];
        sx[2 * i + 1] = x[(nb + i) * 2 + 1];
    }
    __syncthreads();

    // ---- layer 1 aggregation (dim 2), one thread per node ----
    if (tid < NPG) {
        float di = sdv[tid]; float s2 = di * di;
        float a0 = sx[2 * tid] * s2, a1 = sx[2 * tid + 1] * s2;
        int e0 = g_rowp[nb + tid], e1 = g_rowp[nb + tid + 1];
        for (int e = e0; e < e1; e++) {
            int c = g_ecol[e]; float nr = g_enorm[e];
            a0 += sx[2 * c] * nr;
            a1 += sx[2 * c + 1] * nr;
        }
        sa1[2 * tid] = a0; sa1[2 * tid + 1] = a1;
    }
    __syncthreads();

    // ---- layer 1 transform + LN: warp per node (2 feats/lane) ----
    float2* sh2 = (float2*)sh;
    for (int n = wid; n < NPG; n += 8) {
        float a0 = sa1[2 * n], a1 = sa1[2 * n + 1];
        int j = 2 * lane;
        float v0 = fmaxf(a0 * sW1[j]     + a1 * sW1[64 + j]     + sb1[j],     0.f);
        float v1 = fmaxf(a0 * sW1[j + 1] + a1 * sW1[64 + j + 1] + sb1[j + 1], 0.f);
        float s = v0 + v1, q = v0 * v0 + v1 * v1;
        #pragma unroll
        for (int o = 16; o; o >>= 1) {
            s += __shfl_xor_sync(0xffffffffu, s, o);
            q += __shfl_xor_sync(0xffffffffu, q, o);
        }
        float m = s * (1.f / 64.f);
        float inv = rsqrtf(q * (1.f / 64.f) - m * m + 1e-5f);
        sh2[n * 32 + lane] = make_float2((v0 - m) * inv * sg1[j]     + sbe1[j],
                                         (v1 - m) * inv * sg1[j + 1] + sbe1[j + 1]);
    }
    __syncthreads();

    // ---- layer 2 aggregation: warp per node, CSR, float2 lanes ----
    float2* sag2 = (float2*)sag;
    for (int n = wid; n < NPG; n += 8) {
        float di = sdv[n]; float s2 = di * di;
        float2 h = sh2[n * 32 + lane];
        float acc0 = h.x * s2, acc1 = h.y * s2;
        int e0 = g_rowp[nb + n], e1 = g_rowp[nb + n + 1];
        for (int e = e0; e < e1; e++) {
            int c = g_ecol[e]; float nr = g_enorm[e];
            float2 hv = sh2[c * 32 + lane];
            acc0 += hv.x * nr; acc1 += hv.y * nr;
        }
        sag2[n * 32 + lane] = make_float2(acc0, acc1);
    }
    __syncthreads();

    // ---- layer 2 transform + LN: warp handles 25 nodes, 4 at a time ----
    float2* sW2v = (float2*)sW2;
    {
        int nstart = wid * 25, nend = nstart + 25;
        for (int n4 = nstart; n4 < nend; n4 += 4) {
            int cnt = nend - n4; if (cnt > 4) cnt = 4;
            float acc[4][2] = {};
            for (int k = 0; k < 64; k++) {
                float2 w = sW2v[k * 32 + lane];
                #pragma unroll
                for (int u = 0; u < 4; u++) {
                    if (u < cnt) {
                        float a = sag[(n4 + u) * 64 + k];
                        acc[u][0] += a * w.x; acc[u][1] += a * w.y;
                    }
                }
            }
            int j = 2 * lane;
            #pragma unroll
            for (int u = 0; u < 4; u++) {
                if (u < cnt) {
                    int n = n4 + u;
                    float v0 = fmaxf(acc[u][0] + sb2[j],     0.f);
                    float v1 = fmaxf(acc[u][1] + sb2[j + 1], 0.f);
                    float s = v0 + v1, q = v0 * v0 + v1 * v1;
                    #pragma unroll
                    for (int o = 16; o; o >>= 1) {
                        s += __shfl_xor_sync(0xffffffffu, s, o);
                        q += __shfl_xor_sync(0xffffffffu, q, o);
                    }
                    float m = s * (1.f / 64.f);
                    float inv = rsqrtf(q * (1.f / 64.f) - m * m + 1e-5f);
                    sh2[n * 32 + lane] = make_float2((v0 - m) * inv * sg2[j]     + sbe2[j],
                                                     (v1 - m) * inv * sg2[j + 1] + sbe2[j + 1]);
                }
            }
        }
    }
    __syncthreads();

    // ---- layer 3 agg folded into mean: w_s = dinv_s^2 + sum_out norm ----
    if (tid < NPG) swt[tid] = sdv[tid] * sdv[tid];
    __syncthreads();
    {
        int eb0 = g_rowp[nb], eb1 = g_rowp[nb + NPG];
        for (int e = eb0 + tid; e < eb1; e += 256)
            atomicAdd(&swt[g_ecol[e]], g_enorm[e]);
    }
    __syncthreads();

    // mean_j = (1/200) * sum_n w_n * h2[n][j]
    {
        int quarter = tid >> 6, j = tid & 63;
        float acc = 0.f;
        int n0 = quarter * 50;
        for (int n = n0; n < n0 + 50; n++) acc += swt[n] * sh[n * 64 + j];
        smean[tid] = acc;
    }
    __syncthreads();
    if (tid < 64)
        sa1[tid] = (smean[tid] + smean[64 + tid] + smean[128 + tid] + smean[192 + tid])
                   * (1.f / 200.f);
    __syncthreads();

    // emb = mean @ W3 + b3 + PE -> g_seq
    if (tid < 128) {
        float acc = b3[tid];
        #pragma unroll
        for (int k = 0; k < 64; k++) acc += sa1[k] * W3[k * 128 + tid];
        int ts = g & 63;
        int i2 = tid >> 1;
        float dv  = expf((float)(2 * i2) * (-9.210340371976184f / 128.0f));
        float ang = (float)ts * dv;
        float pe  = (tid & 1) ? cosf(ang) : sinf(ang);
        g_seq[g * 128 + tid] = acc + pe;
    }
}

// =============== transformer ===============
__global__ void k_gemm(const float* __restrict__ A, const float* __restrict__ B,
                       const float* __restrict__ bias, float* __restrict__ C,
                       int M, int N, int K, int relu) {
    __shared__ float As[64][17], Bs[64][17];
    int tx = threadIdx.x, ty = threadIdx.y;
    int tid = ty * 16 + tx;
    int m0 = blockIdx.y * 64, n0 = blockIdx.x * 64;
    float acc[4][4] = {};
    for (int k0 = 0; k0 < K; k0 += 16) {
        #pragma unroll
        for (int i = 0; i < 4; i++) {
            int idx = tid + i * 256;
            int r = idx >> 4, c = idx & 15;
            As[r][c] = A[(m0 + r) * K + k0 + c];
            Bs[r][c] = B[(n0 + r) * K + k0 + c];
        }
        __syncthreads();
        #pragma unroll
        for (int kk = 0; kk < 16; kk++) {
            float a[4], bb[4];
            #pragma unroll
            for (int i = 0; i < 4; i++) a[i]  = As[ty * 4 + i][kk];
            #pragma unroll
            for (int j = 0; j < 4; j++) bb[j] = Bs[tx * 4 + j][kk];
            #pragma unroll
            for (int i = 0; i < 4; i++)
                #pragma unroll
                for (int j = 0; j < 4; j++) acc[i][j] += a[i] * bb[j];
        }
        __syncthreads();
    }
    #pragma unroll
    for (int i = 0; i < 4; i++)
        #pragma unroll
        for (int j = 0; j < 4; j++) {
            float v = acc[i][j] + bias[n0 + tx * 4 + j];
            if (relu) v = fmaxf(v, 0.f);
            C[(m0 + ty * 4 + i) * N + n0 + tx * 4 + j] = v;
        }
}

__global__ void k_gemm_ln(const float* __restrict__ A, const float* __restrict__ B,
                          const float* __restrict__ bias,
                          const float* __restrict__ gam, const float* __restrict__ bet,
                          float* __restrict__ seq, int K) {
    __shared__ float As[64][17], Bs[128][17];
    int tx = threadIdx.x, ty = threadIdx.y;
    int tid = ty * 16 + tx;
    int m0 = blockIdx.x * 64;
    float acc[4][8] = {};
    for (int k0 = 0; k0 < K; k0 += 16) {
        #pragma unroll
        for (int i = 0; i < 4; i++) {
            int idx = tid + i * 256;
            int r = idx >> 4, c = idx & 15;
            As[r][c] = A[(m0 + r) * K + k0 + c];
        }
        #pragma unroll
        for (int i = 0; i < 8; i++) {
            int idx = tid + i * 256;
            int r = idx >> 4, c = idx & 15;
            Bs[r][c] = B[r * K + k0 + c];
        }
        __syncthreads();
        #pragma unroll
        for (int kk = 0; kk < 16; kk++) {
            float a[4], bb[8];
            #pragma unroll
            for (int i = 0; i < 4; i++) a[i]  = As[ty * 4 + i][kk];
            #pragma unroll
            for (int j = 0; j < 8; j++) bb[j] = Bs[tx * 8 + j][kk];
            #pragma unroll
            for (int i = 0; i < 4; i++)
                #pragma unroll
                for (int j = 0; j < 8; j++) acc[i][j] += a[i] * bb[j];
        }
        __syncthreads();
    }
    #pragma unroll
    for (int i = 0; i < 4; i++) {
        int r = m0 + ty * 4 + i;
        float v[8]; float s = 0.f, q = 0.f;
        #pragma unroll
        for (int j = 0; j < 8; j++) {
            int col = tx * 8 + j;
            float t = acc[i][j] + bias[col] + seq[r * 128 + col];
            v[j] = t; s += t; q += t * t;
        }
        #pragma unroll
        for (int o = 8; o; o >>= 1) {
            s += __shfl_xor_sync(0xffffffffu, s, o);
            q += __shfl_xor_sync(0xffffffffu, q, o);
        }
        float m = s * (1.f / 128.f);
        float inv = rsqrtf(q * (1.f / 128.f) - m * m + 1e-5f);
        #pragma unroll
        for (int j = 0; j < 8; j++) {
            int col = tx * 8 + j;
            seq[r * 128 + col] = (v[j] - m) * inv * gam[col] + bet[col];
        }
    }
}

__global__ void k_attn() {
    int bh = blockIdx.x;
    int b = bh >> 2, h = bh & 3;
    int t = threadIdx.x;
    __shared__ float ks[2048], vs[2048];
    for (int idx = t; idx < 2048; idx += 64) {
        int tok = idx >> 5, d = idx & 31;
        const float* row = &g_qkv[(b * 64 + tok) * 384 + h * 32 + d];
        ks[idx] = row[128];
        vs[idx] = row[256];
    }
    float qr[32];
    #pragma unroll
    for (int d = 0; d < 32; d++) qr[d] = g_qkv[(b * 64 + t) * 384 + h * 32 + d];
    __syncthreads();
    float s[64];
    float mx = -1e30f;
    #pragma unroll 4
    for (int j = 0; j < 64; j++) {
        float a = 0.f;
        #pragma unroll
        for (int d = 0; d < 32; d++) a += qr[d] * ks[j * 32 + d];
        a *= 0.17677669529663687f;
        s[j] = a;
        mx = fmaxf(mx, a);
    }
    float sum = 0.f;
    #pragma unroll
    for (int j = 0; j < 64; j++) { s[j] = __expf(s[j] - mx); sum += s[j]; }
    float inv = 1.0f / sum;
    #pragma unroll 4
    for (int d = 0; d < 32; d++) {
        float o = 0.f;
        #pragma unroll
        for (int j = 0; j < 64; j++) o += s[j] * vs[j * 32 + d];
        g_att[(b * 64 + t) * 128 + h * 32 + d] = o * inv;
    }
}

__global__ void k_head(const float* __restrict__ hW1, const float* __restrict__ hb1,
                       const float* __restrict__ hW2, const float* __restrict__ hb2,
                       float* __restrict__ out) {
    int b = blockIdx.x, j = threadIdx.x;   // 128 threads
    __shared__ float p[128];
    __shared__ float hh[64];
    float s = 0.f;
    for (int t = 0; t < 64; t++) s += g_seq[(b * 64 + t) * 128 + j];
    p[j] = s * (1.0f / 64.0f);
    __syncthreads();
    if (j < 64) {
        float a = hb1[j];
        #pragma unroll
        for (int k = 0; k < 128; k++) a += p[k] * hW1[j * 128 + k];
        hh[j] = fmaxf(a, 0.f);
    }
    __syncthreads();
    if (j < 2) {
        float o = hb2[j];
        #pragma unroll
        for (int k = 0; k < 64; k++) o += hh[k] * hW2[j * 64 + k];
        out[b * 2 + j] = o;
    }
}

// =============== host launcher ===============
extern "C" void kernel_launch(void* const* d_in, const int* in_sizes, int n_in,
                              void* d_out, int out_size) {
    const float* x     = (const float*)d_in[0];
    const int*   esrc  = (const int*)d_in[1];
    const int*   edst  = (const int*)d_in[2];
    const float* gW1   = (const float*)d_in[4];
    const float* gb1   = (const float*)d_in[5];
    const float* ln1g  = (const float*)d_in[6];
    const float* ln1b  = (const float*)d_in[7];
    const float* gW2   = (const float*)d_in[8];
    const float* gb2   = (const float*)d_in[9];
    const float* ln2g  = (const float*)d_in[10];
    const float* ln2b  = (const float*)d_in[11];
    const float* gW3   = (const float*)d_in[12];
    const float* gb3   = (const float*)d_in[13];
    const float* tWqkv = (const float*)d_in[14];
    const float* tbqkv = (const float*)d_in[15];
    const float* tWo   = (const float*)d_in[16];
    const float* tbo   = (const float*)d_in[17];
    const float* tg1   = (const float*)d_in[18];
    const float* tb1   = (const float*)d_in[19];
    const float* tg2   = (const float*)d_in[20];
    const float* tb2   = (const float*)d_in[21];
    const float* tWf1  = (const float*)d_in[22];
    const float* tbf1  = (const float*)d_in[23];
    const float* tWf2  = (const float*)d_in[24];
    const float* tbf2  = (const float*)d_in[25];
    const float* hW1   = (const float*)d_in[26];
    const float* hb1   = (const float*)d_in[27];
    const float* hW2   = (const float*)d_in[28];
    const float* hb2   = (const float*)d_in[29];

    float *p_seq, *p_qkv, *p_att, *p_ffn;
    cudaGetSymbolAddress((void**)&p_seq,  g_seq);
    cudaGetSymbolAddress((void**)&p_qkv,  g_qkv);
    cudaGetSymbolAddress((void**)&p_att,  g_att);
    cudaGetSymbolAddress((void**)&p_ffn,  g_ffn);

    cudaFuncSetAttribute(k_mega, cudaFuncAttributeMaxDynamicSharedMemorySize,
                         SM_TOTAL * (int)sizeof(float));

    // CSR prep
    k_prep_zero<<<N_NODES / 256, 256>>>();
    k_count<<<N_EDGES / 256, 256>>>(edst);
    k_dinv<<<N_NODES / 256, 256>>>();
    k_scan1<<<N_GRAPH, 256>>>();
    k_scan2<<<1, 512>>>();
    k_scan3<<<N_NODES / 256, 256>>>();
    k_scatter<<<N_EDGES / 256, 256>>>(esrc, edst);

    // whole GNN + readout + PE
    k_mega<<<N_GRAPH, 256, SM_TOTAL * sizeof(float)>>>(
        x, gW1, gb1, ln1g, ln1b, gW2, gb2, ln2g, ln2b, gW3, gb3);

    // transformer
    dim3 thr(16, 16);
    for (int l = 0; l < NL; l++) {
        k_gemm<<<dim3(384 / 64, 512 / 64), thr>>>(p_seq, tWqkv + l * 384 * 128,
                                                  tbqkv + l * 384, p_qkv, 512, 384, 128, 0);
        k_attn<<<BB * NH, 64>>>();
        k_gemm_ln<<<8, thr>>>(p_att, tWo + l * 128 * 128, tbo + l * 128,
                              tg1 + l * 128, tb1 + l * 128, p_seq, 128);
        k_gemm<<<dim3(512 / 64, 512 / 64), thr>>>(p_seq, tWf1 + l * 512 * 128,
                                                  tbf1 + l * 512, p_ffn, 512, 512, 128, 1);
        k_gemm_ln<<<8, thr>>>(p_ffn, tWf2 + l * 128 * 512, tbf2 + l * 128,
                              tg2 + l * 128, tb2 + l * 128, p_seq, 512);
    }

    // head
    k_head<<<BB, 128>>>(hW1, hb1, hW2, hb2, (float*)d_out);
}

// round 3
// speedup vs baseline: 1.0604x; 1.0604x over previous
#include <cuda_runtime.h>
#include <math.h>

// Problem constants
#define N_NODES 102400
#define N_EDGES 819200
#define N_GRAPH 512
#define NPG     200
#define BB      8
#define TT      64
#define DD      128
#define NH      4
#define DH      32
#define NL      4
#define HID     64

// ---------------- scratch (device globals; no allocation) ----------------
__device__ __align__(256) float g_deg [N_NODES];            // deg -> dinv (in place)
__device__ __align__(256) float g_wt  [N_NODES];            // layer-3 fold weights
__device__ __align__(256) float g_agg1[N_NODES * 2];
__device__ __align__(256) float g_h   [N_NODES * HID];      // h1*dinv then h2
__device__ __align__(256) float g_agg [N_NODES * HID];      // agg2
__device__ __align__(256) float g_seq [BB * TT * DD];
__device__ __align__(256) float g_qkv [BB * TT * 3 * DD];
__device__ __align__(256) float g_att [BB * TT * DD];
__device__ __align__(256) float g_ffn [BB * TT * 4 * DD];

__device__ __forceinline__ void red_add_v4(float* p, float4 v) {
    asm volatile("red.global.add.v4.f32 [%0], {%1,%2,%3,%4};"
                 :: "l"(p), "f"(v.x), "f"(v.y), "f"(v.z), "f"(v.w) : "memory");
}

// ---------------- degree / normalization ----------------
__global__ void k_deg_init() {
    int i = blockIdx.x * blockDim.x + threadIdx.x;
    if (i < N_NODES) g_deg[i] = 1.0f;          // self loop
}
__global__ void k_deg_acc(const int* __restrict__ dst) {
    int e = blockIdx.x * blockDim.x + threadIdx.x;
    if (e < N_EDGES) atomicAdd(&g_deg[dst[e]], 1.0f);
}
// dinv; w init = dinv^2; agg1 init = x * dinv^2
__global__ void k_rsqrt_init(const float* __restrict__ x) {
    int i = blockIdx.x * blockDim.x + threadIdx.x;
    if (i < N_NODES) {
        float di = rsqrtf(g_deg[i]);
        g_deg[i] = di;
        float s = di * di;
        g_wt[i] = s;
        g_agg1[2 * i]     = x[2 * i]     * s;
        g_agg1[2 * i + 1] = x[2 * i + 1] * s;
    }
}
// ---------------- layer-1 edge pass (dim 2) + layer-3 weight accumulation ----------------
__global__ void k_agg1_edges(const float* __restrict__ x,
                             const int* __restrict__ src, const int* __restrict__ dst) {
    int e = blockIdx.x * blockDim.x + threadIdx.x;
    if (e < N_EDGES) {
        int s = src[e], d = dst[e];
        float nr = g_deg[s] * g_deg[d];
        atomicAdd(&g_agg1[2 * d],     x[2 * s]     * nr);
        atomicAdd(&g_agg1[2 * d + 1], x[2 * s + 1] * nr);
        atomicAdd(&g_wt[s], nr);                 // layer-3 fold weight
    }
}

// h1 = LN(relu(agg1 @ W1 + b1)); write g_h = h1*dinv (prescaled), g_agg = h1*dinv^2 (self term)
__global__ void k_l1(const float* __restrict__ W, const float* __restrict__ b,
                     const float* __restrict__ ga, const float* __restrict__ be) {
    int tid  = threadIdx.x;
    int node = blockIdx.x * 4 + (tid >> 6);
    int j    = tid & 63;
    float a0 = g_agg1[node * 2], a1 = g_agg1[node * 2 + 1];
    float v  = fmaxf(a0 * W[j] + a1 * W[64 + j] + b[j], 0.0f);
    float s = v, q = v * v;
    #pragma unroll
    for (int o = 16; o >= 1; o >>= 1) {
        s += __shfl_xor_sync(0xffffffffu, s, o);
        q += __shfl_xor_sync(0xffffffffu, q, o);
    }
    __shared__ float ss[8], sq[8];
    int w = tid >> 5;
    if ((tid & 31) == 0) { ss[w] = s; sq[w] = q; }
    __syncthreads();
    float S = ss[w] + ss[w ^ 1];
    float Q = sq[w] + sq[w ^ 1];
    float m = S * (1.0f / 64.0f);
    float var = Q * (1.0f / 64.0f) - m * m;
    float inv = rsqrtf(var + 1e-5f);
    float h = (v - m) * inv * ga[j] + be[j];
    float di = g_deg[node];
    g_h[node * 64 + j]   = h * di;        // prescaled by dinv_src
    g_agg[node * 64 + j] = h * di * di;   // self-loop init for layer-2 agg
}

// ---------------- layer-2 edge pass: agg[d] += h1s[s] * dinv[d] ----------------
__global__ void k_edges64(const int* __restrict__ src, const int* __restrict__ dst) {
    int t = blockIdx.x * blockDim.x + threadIdx.x;
    if (t < N_EDGES * 16) {
        int e = t >> 4, q = t & 15;
        int s = src[e], d = dst[e];
        float nr = g_deg[d];                 // src scaling prebaked into g_h
        float4 v = reinterpret_cast<const float4*>(g_h)[s * 16 + q];
        v.x *= nr; v.y *= nr; v.z *= nr; v.w *= nr;
        red_add_v4(&g_agg[d * 64 + q * 4], v);
    }
}

// ---------------- layer-2 transform: h2 = LN(relu(agg @ W2 + b2)) -> g_h ----------------
__global__ void k_l2(const float* __restrict__ W, const float* __restrict__ b,
                     const float* __restrict__ ga, const float* __restrict__ be) {
    __shared__ float4 Ws[64 * 16];
    __shared__ float rows[16 * 64];
    __shared__ float bs[64], gs[64], bes[64];
    int tid = threadIdx.x;
    for (int i = tid; i < 1024; i += 256) Ws[i] = reinterpret_cast<const float4*>(W)[i];
    if (tid < 64) { bs[tid] = b[tid]; gs[tid] = ga[tid]; bes[tid] = be[tid]; }
    int base = blockIdx.x * 16 * 64;
    for (int i = tid; i < 1024; i += 256) rows[i] = g_agg[base + i];
    __syncthreads();

    int slot = tid >> 4, jg = tid & 15;
    const float* r = &rows[slot * 64];
    float a0 = 0, a1 = 0, a2 = 0, a3 = 0;
    #pragma unroll
    for (int k = 0; k < 64; k++) {
        float rv = r[k];
        float4 w = Ws[k * 16 + jg];
        a0 += rv * w.x; a1 += rv * w.y; a2 += rv * w.z; a3 += rv * w.w;
    }
    int j0 = jg * 4;
    float v0 = fmaxf(a0 + bs[j0],     0.f);
    float v1 = fmaxf(a1 + bs[j0 + 1], 0.f);
    float v2 = fmaxf(a2 + bs[j0 + 2], 0.f);
    float v3 = fmaxf(a3 + bs[j0 + 3], 0.f);
    float s = v0 + v1 + v2 + v3;
    float q = v0 * v0 + v1 * v1 + v2 * v2 + v3 * v3;
    #pragma unroll
    for (int o = 8; o >= 1; o >>= 1) {
        s += __shfl_xor_sync(0xffffffffu, s, o);
        q += __shfl_xor_sync(0xffffffffu, q, o);
    }
    float m   = s * (1.0f / 64.0f);
    float var = q * (1.0f / 64.0f) - m * m;
    float inv = rsqrtf(var + 1e-5f);
    float4 o4;
    o4.x = (v0 - m) * inv * gs[j0]     + bes[j0];
    o4.y = (v1 - m) * inv * gs[j0 + 1] + bes[j0 + 1];
    o4.z = (v2 - m) * inv * gs[j0 + 2] + bes[j0 + 2];
    o4.w = (v3 - m) * inv * gs[j0 + 3] + bes[j0 + 3];
    reinterpret_cast<float4*>(g_h)[(blockIdx.x * 16 + slot) * 16 + jg] = o4;
}

// ---------------- readout: emb = (1/200) Σ w_n h2[n] @ W3 + b3 + PE ----------------
__global__ void k_graph_emb(const float* __restrict__ W3, const float* __restrict__ b3) {
    int gidx = blockIdx.x, t = threadIdx.x;   // 128 threads
    __shared__ float part[128];
    __shared__ float am[64];
    __shared__ float wts[NPG];
    for (int i = t; i < NPG; i += 128) wts[i] = g_wt[gidx * NPG + i];
    __syncthreads();
    int j = t & 63, half = t >> 6;
    const float* base = &g_h[(gidx * NPG + half * 100) * 64];
    const float* wb = &wts[half * 100];
    float s = 0.f;
    for (int n = 0; n < 100; n++) s += wb[n] * base[n * 64 + j];
    part[t] = s;
    __syncthreads();
    if (t < 64) am[t] = (part[t] + part[t + 64]) * (1.0f / 200.0f);
    __syncthreads();
    float acc = b3[t];
    #pragma unroll
    for (int k = 0; k < 64; k++) acc += am[k] * W3[k * 128 + t];
    int ts = gidx & 63;
    int i2 = t >> 1;
    float dv  = expf((float)(2 * i2) * (-9.210340371976184f / 128.0f));
    float ang = (float)ts * dv;
    float pe  = (t & 1) ? cosf(ang) : sinf(ang);
    g_seq[gidx * 128 + t] = acc + pe;
}

// =============== transformer ===============
__global__ void k_gemm(const float* __restrict__ A, const float* __restrict__ B,
                       const float* __restrict__ bias, float* __restrict__ C,
                       int M, int N, int K, int relu) {
    __shared__ float As[64][17], Bs[64][17];
    int tx = threadIdx.x, ty = threadIdx.y;
    int tid = ty * 16 + tx;
    int m0 = blockIdx.y * 64, n0 = blockIdx.x * 64;
    float acc[4][4] = {};
    for (int k0 = 0; k0 < K; k0 += 16) {
        #pragma unroll
        for (int i = 0; i < 4; i++) {
            int idx = tid + i * 256;
            int r = idx >> 4, c = idx & 15;
            As[r][c] = A[(m0 + r) * K + k0 + c];
            Bs[r][c] = B[(n0 + r) * K + k0 + c];
        }
        __syncthreads();
        #pragma unroll
        for (int kk = 0; kk < 16; kk++) {
            float a[4], bb[4];
            #pragma unroll
            for (int i = 0; i < 4; i++) a[i]  = As[ty * 4 + i][kk];
            #pragma unroll
            for (int j = 0; j < 4; j++) bb[j] = Bs[tx * 4 + j][kk];
            #pragma unroll
            for (int i = 0; i < 4; i++)
                #pragma unroll
                for (int j = 0; j < 4; j++) acc[i][j] += a[i] * bb[j];
        }
        __syncthreads();
    }
    #pragma unroll
    for (int i = 0; i < 4; i++)
        #pragma unroll
        for (int j = 0; j < 4; j++) {
            float v = acc[i][j] + bias[n0 + tx * 4 + j];
            if (relu) v = fmaxf(v, 0.f);
            C[(m0 + ty * 4 + i) * N + n0 + tx * 4 + j] = v;
        }
}

// fused GEMM (N=128) + residual + LN; 32 rows per block (grid 16)
__global__ void k_gemm_ln(const float* __restrict__ A, const float* __restrict__ B,
                          const float* __restrict__ bias,
                          const float* __restrict__ gam, const float* __restrict__ bet,
                          float* __restrict__ seq, int K) {
    __shared__ float As[32][17], Bs[128][17];
    int tx = threadIdx.x, ty = threadIdx.y;
    int tid = ty * 16 + tx;
    int m0 = blockIdx.x * 32;
    float acc[2][8] = {};
    for (int k0 = 0; k0 < K; k0 += 16) {
        #pragma unroll
        for (int i = 0; i < 2; i++) {
            int idx = tid + i * 256;
            int r = idx >> 4, c = idx & 15;
            As[r][c] = A[(m0 + r) * K + k0 + c];
        }
        #pragma unroll
        for (int i = 0; i < 8; i++) {
            int idx = tid + i * 256;
            int r = idx >> 4, c = idx & 15;
            Bs[r][c] = B[r * K + k0 + c];
        }
        __syncthreads();
        #pragma unroll
        for (int kk = 0; kk < 16; kk++) {
            float a[2], bb[8];
            #pragma unroll
            for (int i = 0; i < 2; i++) a[i]  = As[ty * 2 + i][kk];
            #pragma unroll
            for (int j = 0; j < 8; j++) bb[j] = Bs[tx * 8 + j][kk];
            #pragma unroll
            for (int i = 0; i < 2; i++)
                #pragma unroll
                for (int j = 0; j < 8; j++) acc[i][j] += a[i] * bb[j];
        }
        __syncthreads();
    }
    #pragma unroll
    for (int i = 0; i < 2; i++) {
        int r = m0 + ty * 2 + i;
        float v[8]; float s = 0.f, q = 0.f;
        #pragma unroll
        for (int j = 0; j < 8; j++) {
            int col = tx * 8 + j;
            float t = acc[i][j] + bias[col] + seq[r * 128 + col];
            v[j] = t; s += t; q += t * t;
        }
        #pragma unroll
        for (int o = 8; o; o >>= 1) {
            s += __shfl_xor_sync(0xffffffffu, s, o);
            q += __shfl_xor_sync(0xffffffffu, q, o);
        }
        float m = s * (1.f / 128.f);
        float inv = rsqrtf(q * (1.f / 128.f) - m * m + 1e-5f);
        #pragma unroll
        for (int j = 0; j < 8; j++) {
            int col = tx * 8 + j;
            seq[r * 128 + col] = (v[j] - m) * inv * gam[col] + bet[col];
        }
    }
}

__global__ void k_attn() {
    int bh = blockIdx.x;
    int b = bh >> 2, h = bh & 3;
    int t = threadIdx.x;
    __shared__ float ks[2048], vs[2048];
    for (int idx = t; idx < 2048; idx += 64) {
        int tok = idx >> 5, d = idx & 31;
        const float* row = &g_qkv[(b * 64 + tok) * 384 + h * 32 + d];
        ks[idx] = row[128];
        vs[idx] = row[256];
    }
    float qr[32];
    #pragma unroll
    for (int d = 0; d < 32; d++) qr[d] = g_qkv[(b * 64 + t) * 384 + h * 32 + d];
    __syncthreads();
    float s[64];
    float mx = -1e30f;
    #pragma unroll 4
    for (int j = 0; j < 64; j++) {
        float a = 0.f;
        #pragma unroll
        for (int d = 0; d < 32; d++) a += qr[d] * ks[j * 32 + d];
        a *= 0.17677669529663687f;
        s[j] = a;
        mx = fmaxf(mx, a);
    }
    float sum = 0.f;
    #pragma unroll
    for (int j = 0; j < 64; j++) { s[j] = __expf(s[j] - mx); sum += s[j]; }
    float inv = 1.0f / sum;
    #pragma unroll 4
    for (int d = 0; d < 32; d++) {
        float o = 0.f;
        #pragma unroll
        for (int j = 0; j < 64; j++) o += s[j] * vs[j * 32 + d];
        g_att[(b * 64 + t) * 128 + h * 32 + d] = o * inv;
    }
}

__global__ void k_head(const float* __restrict__ hW1, const float* __restrict__ hb1,
                       const float* __restrict__ hW2, const float* __restrict__ hb2,
                       float* __restrict__ out) {
    int b = blockIdx.x, j = threadIdx.x;   // 128 threads
    __shared__ float p[128];
    __shared__ float hh[64];
    float s = 0.f;
    for (int t = 0; t < 64; t++) s += g_seq[(b * 64 + t) * 128 + j];
    p[j] = s * (1.0f / 64.0f);
    __syncthreads();
    if (j < 64) {
        float a = hb1[j];
        #pragma unroll
        for (int k = 0; k < 128; k++) a += p[k] * hW1[j * 128 + k];
        hh[j] = fmaxf(a, 0.f);
    }
    __syncthreads();
    if (j < 2) {
        float o = hb2[j];
        #pragma unroll
        for (int k = 0; k < 64; k++) o += hh[k] * hW2[j * 64 + k];
        out[b * 2 + j] = o;
    }
}

// =============== host launcher ===============
extern "C" void kernel_launch(void* const* d_in, const int* in_sizes, int n_in,
                              void* d_out, int out_size) {
    const float* x     = (const float*)d_in[0];
    const int*   esrc  = (const int*)d_in[1];
    const int*   edst  = (const int*)d_in[2];
    const float* gW1   = (const float*)d_in[4];
    const float* gb1   = (const float*)d_in[5];
    const float* ln1g  = (const float*)d_in[6];
    const float* ln1b  = (const float*)d_in[7];
    const float* gW2   = (const float*)d_in[8];
    const float* gb2   = (const float*)d_in[9];
    const float* ln2g  = (const float*)d_in[10];
    const float* ln2b  = (const float*)d_in[11];
    const float* gW3   = (const float*)d_in[12];
    const float* gb3   = (const float*)d_in[13];
    const float* tWqkv = (const float*)d_in[14];
    const float* tbqkv = (const float*)d_in[15];
    const float* tWo   = (const float*)d_in[16];
    const float* tbo   = (const float*)d_in[17];
    const float* tg1   = (const float*)d_in[18];
    const float* tb1   = (const float*)d_in[19];
    const float* tg2   = (const float*)d_in[20];
    const float* tb2   = (const float*)d_in[21];
    const float* tWf1  = (const float*)d_in[22];
    const float* tbf1  = (const float*)d_in[23];
    const float* tWf2  = (const float*)d_in[24];
    const float* tbf2  = (const float*)d_in[25];
    const float* hW1   = (const float*)d_in[26];
    const float* hb1   = (const float*)d_in[27];
    const float* hW2   = (const float*)d_in[28];
    const float* hb2   = (const float*)d_in[29];

    float *p_seq, *p_qkv, *p_att, *p_ffn;
    cudaGetSymbolAddress((void**)&p_seq,  g_seq);
    cudaGetSymbolAddress((void**)&p_qkv,  g_qkv);
    cudaGetSymbolAddress((void**)&p_att,  g_att);
    cudaGetSymbolAddress((void**)&p_ffn,  g_ffn);

    // degree / dinv / inits
    k_deg_init<<<N_NODES / 256, 256>>>();
    k_deg_acc<<<N_EDGES / 256, 256>>>(edst);
    k_rsqrt_init<<<N_NODES / 256, 256>>>(x);

    // GCN layer 1 (+ layer-3 fold weights)
    k_agg1_edges<<<N_EDGES / 256, 256>>>(x, esrc, edst);
    k_l1<<<N_NODES / 4, 256>>>(gW1, gb1, ln1g, ln1b);

    // GCN layer 2 (single 64-wide edge pass)
    k_edges64<<<N_EDGES * 16 / 256, 256>>>(esrc, edst);
    k_l2<<<N_NODES / 16, 256>>>(gW2, gb2, ln2g, ln2b);

    // readout (layer-3 folded) + positional encoding
    k_graph_emb<<<N_GRAPH, 128>>>(gW3, gb3);

    // transformer
    dim3 thr(16, 16);
    for (int l = 0; l < NL; l++) {
        k_gemm<<<dim3(384 / 64, 512 / 64), thr>>>(p_seq, tWqkv + l * 384 * 128,
                                                  tbqkv + l * 384, p_qkv, 512, 384, 128, 0);
        k_attn<<<BB * NH, 64>>>();
        k_gemm_ln<<<16, thr>>>(p_att, tWo + l * 128 * 128, tbo + l * 128,
                               tg1 + l * 128, tb1 + l * 128, p_seq, 128);
        k_gemm<<<dim3(512 / 64, 512 / 64), thr>>>(p_seq, tWf1 + l * 512 * 128,
                                                  tbf1 + l * 512, p_ffn, 512, 512, 128, 1);
        k_gemm_ln<<<16, thr>>>(p_ffn, tWf2 + l * 128 * 512, tbf2 + l * 128,
                               tg2 + l * 128, tb2 + l * 128, p_seq, 512);
    }

    // head
    k_head<<<BB, 128>>>(hW1, hb1, hW2, hb2, (float*)d_out);
}

// round 4
// speedup vs baseline: 1.0737x; 1.0125x over previous
#include <cuda_runtime.h>
#include <math.h>

// Problem constants
#define N_NODES 102400
#define N_EDGES 819200
#define N_GRAPH 512
#define NPG     200
#define BB      8
#define TT      64
#define DD      128
#define NH      4
#define DH      32
#define NL      4
#define HID     64

// ---------------- scratch (device globals; no allocation) ----------------
__device__ __align__(256) int   g_indeg [N_NODES];
__device__ __align__(256) int   g_cursor[N_NODES];
__device__ __align__(256) int   g_rowp  [N_NODES + 1];
__device__ __align__(256) int   g_gtot  [N_GRAPH];
__device__ __align__(256) int   g_gbase [N_GRAPH];
__device__ __align__(256) int   g_ecol  [N_EDGES];
__device__ __align__(256) float g_dinv  [N_NODES];
__device__ __align__(256) float g_wt    [N_NODES];          // layer-3 fold weights
__device__ __align__(256) float g_x1    [N_NODES * 2];      // x * dinv (prescaled)
__device__ __align__(256) float g_agg1  [N_NODES * 2];
__device__ __align__(256) float g_h     [N_NODES * HID];    // h1*dinv then h2
__device__ __align__(256) float g_agg   [N_NODES * HID];    // agg2
__device__ __align__(256) float g_seq [BB * TT * DD];
__device__ __align__(256) float g_qkv [BB * TT * 3 * DD];
__device__ __align__(256) float g_att [BB * TT * DD];
__device__ __align__(256) float g_ffn [BB * TT * 4 * DD];

// =============== CSR prep ===============
__global__ void k_zero() {
    int i = blockIdx.x * blockDim.x + threadIdx.x;
    if (i < N_NODES) { g_indeg[i] = 0; g_cursor[i] = 0; }
}
__global__ void k_count(const int* __restrict__ dst) {
    int e = blockIdx.x * blockDim.x + threadIdx.x;
    if (e < N_EDGES) atomicAdd(&g_indeg[dst[e]], 1);
}
// per-graph scan of in-degrees; also dinv, wt init, prescaled x
__global__ void k_scan1(const float* __restrict__ x) {
    __shared__ int buf0[256], buf1[256];
    int g = blockIdx.x, tid = threadIdx.x;
    int n = g * NPG + tid;
    int v = 0;
    if (tid < NPG) {
        v = g_indeg[n];
        float di = rsqrtf((float)(v + 1));
        g_dinv[n] = di;
        g_wt[n]   = di * di;
        g_x1[2 * n]     = x[2 * n]     * di;
        g_x1[2 * n + 1] = x[2 * n + 1] * di;
    }
    int* a = buf0; int* b = buf1;
    a[tid] = v; __syncthreads();
    #pragma unroll
    for (int o = 1; o < 256; o <<= 1) {
        int xv = a[tid];
        if (tid >= o) xv += a[tid - o];
        b[tid] = xv; __syncthreads();
        int* t = a; a = b; b = t;
    }
    if (tid < NPG) g_rowp[n] = a[tid] - v;   // exclusive, graph-local
    if (tid == NPG - 1) g_gtot[g] = a[tid];
}
__global__ void k_scan2() {
    __shared__ int buf0[512], buf1[512];
    int tid = threadIdx.x;
    int v = g_gtot[tid];
    int* a = buf0; int* b = buf1;
    a[tid] = v; __syncthreads();
    #pragma unroll
    for (int o = 1; o < 512; o <<= 1) {
        int xv = a[tid];
        if (tid >= o) xv += a[tid - o];
        b[tid] = xv; __syncthreads();
        int* t = a; a = b; b = t;
    }
    g_gbase[tid] = a[tid] - v;
}
__global__ void k_scan3() {
    int i = blockIdx.x * blockDim.x + threadIdx.x;
    if (i < N_NODES) g_rowp[i] += g_gbase[i / NPG];
    if (i == 0) g_rowp[N_NODES] = N_EDGES;
}
// scatter edges by dst; accumulate layer-3 fold weight on src
__global__ void k_scatter(const int* __restrict__ src, const int* __restrict__ dst) {
    int e = blockIdx.x * blockDim.x + threadIdx.x;
    if (e < N_EDGES) {
        int s = src[e], d = dst[e];
        int pos = g_rowp[d] + atomicAdd(&g_cursor[d], 1);
        g_ecol[pos] = s;
        atomicAdd(&g_wt[s], g_dinv[s] * g_dinv[d]);
    }
}

// =============== GCN layer 1: pull (dim 2), thread per node ===============
__global__ void k_agg1_csr() {
    int n = blockIdx.x * blockDim.x + threadIdx.x;
    if (n < N_NODES) {
        float a0 = g_x1[2 * n], a1 = g_x1[2 * n + 1];   // self (prescaled)
        int e0 = g_rowp[n], e1 = g_rowp[n + 1];
        for (int e = e0; e < e1; e++) {
            int c = g_ecol[e];
            a0 += g_x1[2 * c];
            a1 += g_x1[2 * c + 1];
        }
        float di = g_dinv[n];
        g_agg1[2 * n]     = a0 * di;
        g_agg1[2 * n + 1] = a1 * di;
    }
}

// h1 = LN(relu(agg1 @ W1 + b1)); store prescaled h1*dinv
__global__ void k_l1(const float* __restrict__ W, const float* __restrict__ b,
                     const float* __restrict__ ga, const float* __restrict__ be) {
    int tid  = threadIdx.x;
    int node = blockIdx.x * 4 + (tid >> 6);
    int j    = tid & 63;
    float a0 = g_agg1[node * 2], a1 = g_agg1[node * 2 + 1];
    float v  = fmaxf(a0 * W[j] + a1 * W[64 + j] + b[j], 0.0f);
    float s = v, q = v * v;
    #pragma unroll
    for (int o = 16; o >= 1; o >>= 1) {
        s += __shfl_xor_sync(0xffffffffu, s, o);
        q += __shfl_xor_sync(0xffffffffu, q, o);
    }
    __shared__ float ss[8], sq[8];
    int w = tid >> 5;
    if ((tid & 31) == 0) { ss[w] = s; sq[w] = q; }
    __syncthreads();
    float S = ss[w] + ss[w ^ 1];
    float Q = sq[w] + sq[w ^ 1];
    float m = S * (1.0f / 64.0f);
    float var = Q * (1.0f / 64.0f) - m * m;
    float inv = rsqrtf(var + 1e-5f);
    float h = (v - m) * inv * ga[j] + be[j];
    g_h[node * 64 + j] = h * g_dinv[node];     // prescaled by dinv_src
}

// =============== GCN layer 2: pull, warp per node, float2 lanes ===============
__global__ void k_agg2_csr() {
    int wid_g = (blockIdx.x * blockDim.x + threadIdx.x) >> 5;
    int lane  = threadIdx.x & 31;
    if (wid_g >= N_NODES) return;
    int n = wid_g;
    const float2* h2 = (const float2*)g_h;
    float2 acc = h2[n * 32 + lane];            // self (prescaled)
    int e0 = g_rowp[n], e1 = g_rowp[n + 1];
    int e = e0;
    for (; e + 1 < e1; e += 2) {               // 2-way unroll for MLP
        int c0 = g_ecol[e], c1 = g_ecol[e + 1];
        float2 v0 = h2[c0 * 32 + lane];
        float2 v1 = h2[c1 * 32 + lane];
        acc.x += v0.x + v1.x;
        acc.y += v0.y + v1.y;
    }
    if (e < e1) {
        int c = g_ecol[e];
        float2 v = h2[c * 32 + lane];
        acc.x += v.x; acc.y += v.y;
    }
    float di = g_dinv[n];
    acc.x *= di; acc.y *= di;
    ((float2*)g_agg)[n * 32 + lane] = acc;
}

// ---------------- layer-2 transform: h2 = LN(relu(agg @ W2 + b2)) -> g_h ----------------
__global__ void k_l2(const float* __restrict__ W, const float* __restrict__ b,
                     const float* __restrict__ ga, const float* __restrict__ be) {
    __shared__ float4 Ws[64 * 16];
    __shared__ float rows[16 * 64];
    __shared__ float bs[64], gs[64], bes[64];
    int tid = threadIdx.x;
    for (int i = tid; i < 1024; i += 256) Ws[i] = reinterpret_cast<const float4*>(W)[i];
    if (tid < 64) { bs[tid] = b[tid]; gs[tid] = ga[tid]; bes[tid] = be[tid]; }
    int base = blockIdx.x * 16 * 64;
    for (int i = tid; i < 1024; i += 256) rows[i] = g_agg[base + i];
    __syncthreads();

    int slot = tid >> 4, jg = tid & 15;
    const float* r = &rows[slot * 64];
    float a0 = 0, a1 = 0, a2 = 0, a3 = 0;
    #pragma unroll
    for (int k = 0; k < 64; k++) {
        float rv = r[k];
        float4 w = Ws[k * 16 + jg];
        a0 += rv * w.x; a1 += rv * w.y; a2 += rv * w.z; a3 += rv * w.w;
    }
    int j0 = jg * 4;
    float v0 = fmaxf(a0 + bs[j0],     0.f);
    float v1 = fmaxf(a1 + bs[j0 + 1], 0.f);
    float v2 = fmaxf(a2 + bs[j0 + 2], 0.f);
    float v3 = fmaxf(a3 + bs[j0 + 3], 0.f);
    float s = v0 + v1 + v2 + v3;
    float q = v0 * v0 + v1 * v1 + v2 * v2 + v3 * v3;
    #pragma unroll
    for (int o = 8; o >= 1; o >>= 1) {
        s += __shfl_xor_sync(0xffffffffu, s, o);
        q += __shfl_xor_sync(0xffffffffu, q, o);
    }
    float m   = s * (1.0f / 64.0f);
    float var = q * (1.0f / 64.0f) - m * m;
    float inv = rsqrtf(var + 1e-5f);
    float4 o4;
    o4.x = (v0 - m) * inv * gs[j0]     + bes[j0];
    o4.y = (v1 - m) * inv * gs[j0 + 1] + bes[j0 + 1];
    o4.z = (v2 - m) * inv * gs[j0 + 2] + bes[j0 + 2];
    o4.w = (v3 - m) * inv * gs[j0 + 3] + bes[j0 + 3];
    reinterpret_cast<float4*>(g_h)[(blockIdx.x * 16 + slot) * 16 + jg] = o4;
}

// ---------------- readout: emb = (1/200) Σ w_n h2[n] @ W3 + b3 + PE ----------------
__global__ void k_graph_emb(const float* __restrict__ W3, const float* __restrict__ b3) {
    int gidx = blockIdx.x, t = threadIdx.x;   // 128 threads
    __shared__ float part[128];
    __shared__ float am[64];
    __shared__ float wts[NPG];
    for (int i = t; i < NPG; i += 128) wts[i] = g_wt[gidx * NPG + i];
    __syncthreads();
    int j = t & 63, half = t >> 6;
    const float* base = &g_h[(gidx * NPG + half * 100) * 64];
    const float* wb = &wts[half * 100];
    float s = 0.f;
    for (int n = 0; n < 100; n++) s += wb[n] * base[n * 64 + j];
    part[t] = s;
    __syncthreads();
    if (t < 64) am[t] = (part[t] + part[t + 64]) * (1.0f / 200.0f);
    __syncthreads();
    float acc = b3[t];
    #pragma unroll
    for (int k = 0; k < 64; k++) acc += am[k] * W3[k * 128 + t];
    int ts = gidx & 63;
    int i2 = t >> 1;
    float dv  = expf((float)(2 * i2) * (-9.210340371976184f / 128.0f));
    float ang = (float)ts * dv;
    float pe  = (t & 1) ? cosf(ang) : sinf(ang);
    g_seq[gidx * 128 + t] = acc + pe;
}

// =============== transformer ===============
__global__ void k_gemm(const float* __restrict__ A, const float* __restrict__ B,
                       const float* __restrict__ bias, float* __restrict__ C,
                       int M, int N, int K, int relu) {
    __shared__ float As[64][17], Bs[64][17];
    int tx = threadIdx.x, ty = threadIdx.y;
    int tid = ty * 16 + tx;
    int m0 = blockIdx.y * 64, n0 = blockIdx.x * 64;
    float acc[4][4] = {};
    for (int k0 = 0; k0 < K; k0 += 16) {
        #pragma unroll
        for (int i = 0; i < 4; i++) {
            int idx = tid + i * 256;
            int r = idx >> 4, c = idx & 15;
            As[r][c] = A[(m0 + r) * K + k0 + c];
            Bs[r][c] = B[(n0 + r) * K + k0 + c];
        }
        __syncthreads();
        #pragma unroll
        for (int kk = 0; kk < 16; kk++) {
            float a[4], bb[4];
            #pragma unroll
            for (int i = 0; i < 4; i++) a[i]  = As[ty * 4 + i][kk];
            #pragma unroll
            for (int j = 0; j < 4; j++) bb[j] = Bs[tx * 4 + j][kk];
            #pragma unroll
            for (int i = 0; i < 4; i++)
                #pragma unroll
                for (int j = 0; j < 4; j++) acc[i][j] += a[i] * bb[j];
        }
        __syncthreads();
    }
    #pragma unroll
    for (int i = 0; i < 4; i++)
        #pragma unroll
        for (int j = 0; j < 4; j++) {
            float v = acc[i][j] + bias[n0 + tx * 4 + j];
            if (relu) v = fmaxf(v, 0.f);
            C[(m0 + ty * 4 + i) * N + n0 + tx * 4 + j] = v;
        }
}

// fused GEMM (N=128) + residual + LN; 32 rows per block (grid 16)
__global__ void k_gemm_ln(const float* __restrict__ A, const float* __restrict__ B,
                          const float* __restrict__ bias,
                          const float* __restrict__ gam, const float* __restrict__ bet,
                          float* __restrict__ seq, int K) {
    __shared__ float As[32][17], Bs[128][17];
    int tx = threadIdx.x, ty = threadIdx.y;
    int tid = ty * 16 + tx;
    int m0 = blockIdx.x * 32;
    float acc[2][8] = {};
    for (int k0 = 0; k0 < K; k0 += 16) {
        #pragma unroll
        for (int i = 0; i < 2; i++) {
            int idx = tid + i * 256;
            int r = idx >> 4, c = idx & 15;
            As[r][c] = A[(m0 + r) * K + k0 + c];
        }
        #pragma unroll
        for (int i = 0; i < 8; i++) {
            int idx = tid + i * 256;
            int r = idx >> 4, c = idx & 15;
            Bs[r][c] = B[r * K + k0 + c];
        }
        __syncthreads();
        #pragma unroll
        for (int kk = 0; kk < 16; kk++) {
            float a[2], bb[8];
            #pragma unroll
            for (int i = 0; i < 2; i++) a[i]  = As[ty * 2 + i][kk];
            #pragma unroll
            for (int j = 0; j < 8; j++) bb[j] = Bs[tx * 8 + j][kk];
            #pragma unroll
            for (int i = 0; i < 2; i++)
                #pragma unroll
                for (int j = 0; j < 8; j++) acc[i][j] += a[i] * bb[j];
        }
        __syncthreads();
    }
    #pragma unroll
    for (int i = 0; i < 2; i++) {
        int r = m0 + ty * 2 + i;
        float v[8]; float s = 0.f, q = 0.f;
        #pragma unroll
        for (int j = 0; j < 8; j++) {
            int col = tx * 8 + j;
            float t = acc[i][j] + bias[col] + seq[r * 128 + col];
            v[j] = t; s += t; q += t * t;
        }
        #pragma unroll
        for (int o = 8; o; o >>= 1) {
            s += __shfl_xor_sync(0xffffffffu, s, o);
            q += __shfl_xor_sync(0xffffffffu, q, o);
        }
        float m = s * (1.f / 128.f);
        float inv = rsqrtf(q * (1.f / 128.f) - m * m + 1e-5f);
        #pragma unroll
        for (int j = 0; j < 8; j++) {
            int col = tx * 8 + j;
            seq[r * 128 + col] = (v[j] - m) * inv * gam[col] + bet[col];
        }
    }
}

__global__ void k_attn() {
    int bh = blockIdx.x;
    int b = bh >> 2, h = bh & 3;
    int t = threadIdx.x;
    __shared__ float ks[2048], vs[2048];
    for (int idx = t; idx < 2048; idx += 64) {
        int tok = idx >> 5, d = idx & 31;
        const float* row = &g_qkv[(b * 64 + tok) * 384 + h * 32 + d];
        ks[idx] = row[128];
        vs[idx] = row[256];
    }
    float qr[32];
    #pragma unroll
    for (int d = 0; d < 32; d++) qr[d] = g_qkv[(b * 64 + t) * 384 + h * 32 + d];
    __syncthreads();
    float s[64];
    float mx = -1e30f;
    #pragma unroll 4
    for (int j = 0; j < 64; j++) {
        float a = 0.f;
        #pragma unroll
        for (int d = 0; d < 32; d++) a += qr[d] * ks[j * 32 + d];
        a *= 0.17677669529663687f;
        s[j] = a;
        mx = fmaxf(mx, a);
    }
    float sum = 0.f;
    #pragma unroll
    for (int j = 0; j < 64; j++) { s[j] = __expf(s[j] - mx); sum += s[j]; }
    float inv = 1.0f / sum;
    #pragma unroll 4
    for (int d = 0; d < 32; d++) {
        float o = 0.f;
        #pragma unroll
        for (int j = 0; j < 64; j++) o += s[j] * vs[j * 32 + d];
        g_att[(b * 64 + t) * 128 + h * 32 + d] = o * inv;
    }
}

__global__ void k_head(const float* __restrict__ hW1, const float* __restrict__ hb1,
                       const float* __restrict__ hW2, const float* __restrict__ hb2,
                       float* __restrict__ out) {
    int b = blockIdx.x, j = threadIdx.x;   // 128 threads
    __shared__ float p[128];
    __shared__ float hh[64];
    float s = 0.f;
    for (int t = 0; t < 64; t++) s += g_seq[(b * 64 + t) * 128 + j];
    p[j] = s * (1.0f / 64.0f);
    __syncthreads();
    if (j < 64) {
        float a = hb1[j];
        #pragma unroll
        for (int k = 0; k < 128; k++) a += p[k] * hW1[j * 128 + k];
        hh[j] = fmaxf(a, 0.f);
    }
    __syncthreads();
    if (j < 2) {
        float o = hb2[j];
        #pragma unroll
        for (int k = 0; k < 64; k++) o += hh[k] * hW2[j * 64 + k];
        out[b * 2 + j] = o;
    }
}

// =============== host launcher ===============
extern "C" void kernel_launch(void* const* d_in, const int* in_sizes, int n_in,
                              void* d_out, int out_size) {
    const float* x     = (const float*)d_in[0];
    const int*   esrc  = (const int*)d_in[1];
    const int*   edst  = (const int*)d_in[2];
    const float* gW1   = (const float*)d_in[4];
    const float* gb1   = (const float*)d_in[5];
    const float* ln1g  = (const float*)d_in[6];
    const float* ln1b  = (const float*)d_in[7];
    const float* gW2   = (const float*)d_in[8];
    const float* gb2   = (const float*)d_in[9];
    const float* ln2g  = (const float*)d_in[10];
    const float* ln2b  = (const float*)d_in[11];
    const float* gW3   = (const float*)d_in[12];
    const float* gb3   = (const float*)d_in[13];
    const float* tWqkv = (const float*)d_in[14];
    const float* tbqkv = (const float*)d_in[15];
    const float* tWo   = (const float*)d_in[16];
    const float* tbo   = (const float*)d_in[17];
    const float* tg1   = (const float*)d_in[18];
    const float* tb1   = (const float*)d_in[19];
    const float* tg2   = (const float*)d_in[20];
    const float* tb2   = (const float*)d_in[21];
    const float* tWf1  = (const float*)d_in[22];
    const float* tbf1  = (const float*)d_in[23];
    const float* tWf2  = (const float*)d_in[24];
    const float* tbf2  = (const float*)d_in[25];
    const float* hW1   = (const float*)d_in[26];
    const float* hb1   = (const float*)d_in[27];
    const float* hW2   = (const float*)d_in[28];
    const float* hb2   = (const float*)d_in[29];

    float *p_seq, *p_qkv, *p_att, *p_ffn;
    cudaGetSymbolAddress((void**)&p_seq,  g_seq);
    cudaGetSymbolAddress((void**)&p_qkv,  g_qkv);
    cudaGetSymbolAddress((void**)&p_att,  g_att);
    cudaGetSymbolAddress((void**)&p_ffn,  g_ffn);

    // CSR prep (atomic-free aggregation afterwards)
    k_zero<<<N_NODES / 256, 256>>>();
    k_count<<<N_EDGES / 256, 256>>>(edst);
    k_scan1<<<N_GRAPH, 256>>>(x);
    k_scan2<<<1, 512>>>();
    k_scan3<<<N_NODES / 256, 256>>>();
    k_scatter<<<N_EDGES / 256, 256>>>(esrc, edst);

    // GCN layer 1 (pull)
    k_agg1_csr<<<N_NODES / 256, 256>>>();
    k_l1<<<N_NODES / 4, 256>>>(gW1, gb1, ln1g, ln1b);

    // GCN layer 2 (pull, warp per node)
    k_agg2_csr<<<N_NODES * 32 / 256, 256>>>();
    k_l2<<<N_NODES / 16, 256>>>(gW2, gb2, ln2g, ln2b);

    // readout (layer-3 folded) + positional encoding
    k_graph_emb<<<N_GRAPH, 128>>>(gW3, gb3);

    // transformer
    dim3 thr(16, 16);
    for (int l = 0; l < NL; l++) {
        k_gemm<<<dim3(384 / 64, 512 / 64), thr>>>(p_seq, tWqkv + l * 384 * 128,
                                                  tbqkv + l * 384, p_qkv, 512, 384, 128, 0);
        k_attn<<<BB * NH, 64>>>();
        k_gemm_ln<<<16, thr>>>(p_att, tWo + l * 128 * 128, tbo + l * 128,
                               tg1 + l * 128, tb1 + l * 128, p_seq, 128);
        k_gemm<<<dim3(512 / 64, 512 / 64), thr>>>(p_seq, tWf1 + l * 512 * 128,
                                                  tbf1 + l * 512, p_ffn, 512, 512, 128, 1);
        k_gemm_ln<<<16, thr>>>(p_ffn, tWf2 + l * 128 * 512, tbf2 + l * 128,
                               tg2 + l * 128, tb2 + l * 128, p_seq, 512);
    }

    // head
    k_head<<<BB, 128>>>(hW1, hb1, hW2, hb2, (float*)d_out);
}